// round 6
// baseline (speedup 1.0000x reference)
#include <cuda_runtime.h>
#include <cuda_fp16.h>
#include <math.h>

#define BB   8
#define NPTS 8192
#define SS   2048
#define CC   256
#define KNN  8

#define KNN_BLOCKS   (BB * NPTS / 256)          // 256 blocks, 256 thr each
#define TR_BLOCKS    ((SS / 32) * (CC / 32) * BB) // 4096 blocks

// Scratch (no allocation allowed)
__device__ __half g_featH[BB * SS * CC];       // [B][S][C] fp16, 8.4 MB
__device__ int    g_idx[BB * NPTS * KNN];      // 2 MB
__device__ float  g_w  [BB * NPTS * KNN];      // 2 MB

// ---------------------------------------------------------------------------
// Fused kernel: knn blocks first (long-running), transpose blocks fill in.
// Both are independent; fusing overlaps the 12us transpose under knn.
// ---------------------------------------------------------------------------
extern __shared__ char smem_raw[];

__device__ void knn_part(const float* __restrict__ xyz,
                         const float* __restrict__ sxyz,
                         int blk, int tid) {
    float4* sp = (float4*)smem_raw;            // 2048 x 16B = 32 KB
    int b    = blk / (NPTS / 256);
    int tile = blk % (NPTS / 256);

    const float* sb = sxyz + (size_t)b * 3 * SS;
    for (int s = tid; s < SS; s += 256) {
        sp[s] = make_float4(sb[s], sb[SS + s], sb[2 * SS + s], 0.0f);
    }
    __syncthreads();

    int n = tile * 256 + tid;
    const float* xb = xyz + (size_t)b * 3 * NPTS;
    float qx = xb[n];
    float qy = xb[NPTS + n];
    float qz = xb[2 * NPTS + n];

    float dist[KNN];     // descending: dist[0] = current max
    int   nidx[KNN];
    #pragma unroll
    for (int k = 0; k < KNN; k++) { dist[k] = 3.4e38f; nidx[k] = 0; }

    #pragma unroll 4
    for (int s = 0; s < SS; s++) {
        float4 p = sp[s];
        float dx = qx - p.x;
        float dy = qy - p.y;
        float dz = qz - p.z;
        float d = fmaf(dx, dx, fmaf(dy, dy, dz * dz));
        bool c0 = d < dist[0];
        // Warp-uniform gate: no divergence machinery, no if-conversion of
        // the whole body into the hot loop. Body is a per-lane no-op when
        // c0 is false (all c_k false => new[k] = old[k]).
        if (__any_sync(0xffffffffu, c0)) {
            bool c1 = d < dist[1];
            bool c2 = d < dist[2];
            bool c3 = d < dist[3];
            bool c4 = d < dist[4];
            bool c5 = d < dist[5];
            bool c6 = d < dist[6];
            bool c7 = d < dist[7];
            float n0 = c1 ? dist[1] : (c0 ? d : dist[0]);
            int   m0 = c1 ? nidx[1] : (c0 ? s : nidx[0]);
            float n1 = c2 ? dist[2] : (c1 ? d : dist[1]);
            int   m1 = c2 ? nidx[2] : (c1 ? s : nidx[1]);
            float n2 = c3 ? dist[3] : (c2 ? d : dist[2]);
            int   m2 = c3 ? nidx[3] : (c2 ? s : nidx[2]);
            float n3 = c4 ? dist[4] : (c3 ? d : dist[3]);
            int   m3 = c4 ? nidx[4] : (c3 ? s : nidx[3]);
            float n4 = c5 ? dist[5] : (c4 ? d : dist[4]);
            int   m4 = c5 ? nidx[5] : (c4 ? s : nidx[4]);
            float n5 = c6 ? dist[6] : (c5 ? d : dist[5]);
            int   m5 = c6 ? nidx[6] : (c5 ? s : nidx[5]);
            float n6 = c7 ? dist[7] : (c6 ? d : dist[6]);
            int   m6 = c7 ? nidx[7] : (c6 ? s : nidx[6]);
            float n7 = c7 ? d : dist[7];
            int   m7 = c7 ? s : nidx[7];
            dist[0] = n0; nidx[0] = m0;
            dist[1] = n1; nidx[1] = m1;
            dist[2] = n2; nidx[2] = m2;
            dist[3] = n3; nidx[3] = m3;
            dist[4] = n4; nidx[4] = m4;
            dist[5] = n5; nidx[5] = m5;
            dist[6] = n6; nidx[6] = m6;
            dist[7] = n7; nidx[7] = m7;
        }
    }

    // inverse-distance weights (reference formula)
    float inv[KNN];
    float ws = 0.0f;
    #pragma unroll
    for (int k = 0; k < KNN; k++) {
        float dd = sqrtf(dist[k]);
        dd = fmaxf(dd, 1e-10f);
        inv[k] = 1.0f / dd;
        ws += inv[k];
    }
    float rws = 1.0f / ws;

    int base = (b * NPTS + n) * KNN;
    #pragma unroll
    for (int k = 0; k < KNN; k++) {
        g_idx[base + k] = nidx[k];
        g_w[base + k]   = inv[k] * rws;
    }
}

__device__ void transpose_part(const float* __restrict__ feat,
                               int blk, int tid) {
    float (*tile)[33] = (float (*)[33])smem_raw;   // 32 x 33 floats
    int s0 = (blk % (SS / 32)) * 32;
    int c0 = ((blk / (SS / 32)) % (CC / 32)) * 32;
    int b  = blk / ((SS / 32) * (CC / 32));
    int tx = tid & 31;
    int ty = tid >> 5;            // 0..7

    const float* src = feat + (size_t)b * CC * SS;
    #pragma unroll
    for (int i = ty; i < 32; i += 8) {
        tile[i][tx] = src[(size_t)(c0 + i) * SS + s0 + tx];
    }
    __syncthreads();
    __half* dst = g_featH + (size_t)b * SS * CC;
    #pragma unroll
    for (int i = ty; i < 32; i += 8) {
        dst[(size_t)(s0 + i) * CC + c0 + tx] = __float2half(tile[tx][i]);
    }
}

__global__ void __launch_bounds__(256)
fused_pre_kernel(const float* __restrict__ feat,
                 const float* __restrict__ xyz,
                 const float* __restrict__ sxyz) {
    int blk = blockIdx.x;
    if (blk < KNN_BLOCKS) {
        knn_part(xyz, sxyz, blk, threadIdx.x);
    } else {
        transpose_part(feat, blk - KNN_BLOCKS, threadIdx.x);
    }
}

// ---------------------------------------------------------------------------
// Kernel 2: weighted feature interpolation, fp16 gathers, fp32 accumulate.
// Block = 32 queries, 1024 threads.
// Phase 1: lanes span channels -> each (q,k) gather is 512B contiguous.
// Phase 2: warp per channel row, lanes along n -> coalesced fp32 STG.
// ---------------------------------------------------------------------------
__global__ void interp_kernel(float* __restrict__ out) {
    __shared__ float tile[32][CC + 1];   // 32 x 257 floats = 32.9 KB
    __shared__ int   s_idx[32][KNN];
    __shared__ float s_w[32][KNN];

    int b  = blockIdx.y;
    int n0 = blockIdx.x * 32;
    int tid = threadIdx.x;

    if (tid < 32 * KNN) {
        int nn = tid / KNN;
        int kk = tid % KNN;
        int base = (b * NPTS + n0 + nn) * KNN;
        s_idx[nn][kk] = g_idx[base + kk];
        s_w[nn][kk]   = g_w[base + kk];
    }
    __syncthreads();

    int tc    = tid & 63;
    int qbase = tid >> 6;            // 0..15, each handles 2 queries
    const __half* fb = g_featH + (size_t)b * SS * CC + tc * 4;

    #pragma unroll
    for (int q = qbase; q < 32; q += 16) {
        float a0 = 0.f, a1 = 0.f, a2 = 0.f, a3 = 0.f;
        #pragma unroll
        for (int k = 0; k < KNN; k++) {
            int   si = s_idx[q][k];
            float wt = s_w[q][k];
            uint2 raw = *(const uint2*)(fb + (size_t)si * CC);
            __half2 h0 = *reinterpret_cast<__half2*>(&raw.x);
            __half2 h1 = *reinterpret_cast<__half2*>(&raw.y);
            float2 f0 = __half22float2(h0);
            float2 f1 = __half22float2(h1);
            a0 = fmaf(wt, f0.x, a0);
            a1 = fmaf(wt, f0.y, a1);
            a2 = fmaf(wt, f1.x, a2);
            a3 = fmaf(wt, f1.y, a3);
        }
        int c = tc * 4;
        tile[q][c + 0] = a0;
        tile[q][c + 1] = a1;
        tile[q][c + 2] = a2;
        tile[q][c + 3] = a3;
    }
    __syncthreads();

    int lane = tid & 31;
    int w    = tid >> 5;
    float* ob = out + (size_t)b * CC * NPTS + n0 + lane;
    #pragma unroll
    for (int j = 0; j < 8; j++) {
        int c = w + j * 32;
        ob[(size_t)c * NPTS] = tile[lane][c];
    }
}

// ---------------------------------------------------------------------------
extern "C" void kernel_launch(void* const* d_in, const int* in_sizes, int n_in,
                              void* d_out, int out_size) {
    const float* xyz         = (const float*)d_in[0];  // [B,3,N]
    const float* sparse_xyz  = (const float*)d_in[1];  // [B,3,S]
    const float* sparse_feat = (const float*)d_in[2];  // [B,C,S]
    float* out = (float*)d_out;                        // [B,C,N]

    // knn blocks first so they start immediately; transpose fills idle SMs.
    fused_pre_kernel<<<KNN_BLOCKS + TR_BLOCKS, 256, SS * sizeof(float4)>>>(
        sparse_feat, xyz, sparse_xyz);
    interp_kernel<<<dim3(NPTS / 32, BB), 1024>>>(out);
}

// round 7
// speedup vs baseline: 1.2647x; 1.2647x over previous
#include <cuda_runtime.h>
#include <cuda_fp16.h>
#include <math.h>

#define BB   8
#define NPTS 8192
#define SS   2048
#define CC   256
#define KNN  8

// Scratch (no allocation allowed)
__device__ __half g_featH[BB * SS * CC];       // [B][S][C] fp16, 8.4 MB
__device__ int    g_idx[BB * NPTS * KNN];      // 2 MB
__device__ float  g_w  [BB * NPTS * KNN];      // 2 MB

// ---------------------------------------------------------------------------
// Kernel 0: transpose + fp16-convert sparse_feat [B,C,S] -> g_featH [B,S,C]
// ---------------------------------------------------------------------------
__global__ void transpose_feat_kernel(const float* __restrict__ feat) {
    __shared__ float tile[32][33];
    int b  = blockIdx.z;
    int s0 = blockIdx.x * 32;
    int c0 = blockIdx.y * 32;
    const float* src = feat + (size_t)b * CC * SS;

    #pragma unroll
    for (int i = threadIdx.y; i < 32; i += 8) {
        tile[i][threadIdx.x] = src[(size_t)(c0 + i) * SS + s0 + threadIdx.x];
    }
    __syncthreads();
    __half* dst = g_featH + (size_t)b * SS * CC;
    #pragma unroll
    for (int i = threadIdx.y; i < 32; i += 8) {
        dst[(size_t)(s0 + i) * CC + c0 + threadIdx.x] =
            __float2half(tile[threadIdx.x][i]);
    }
}

// ---------------------------------------------------------------------------
// Kernel 1: brute-force KNN (K=8) + inverse-distance weights.
// Direct (p-q)^2 selection metric (REQUIRED — R2 lesson).
// Group-of-4 gating: 4 branch-free distances, one fmin-reduce, ONE warp vote;
// per-point gated parallel-shift inserts only inside taken groups.
// 512 blocks x 128 threads (R6's 256-block layout load-imbalanced — reverted).
// ---------------------------------------------------------------------------
#define INSERT_POINT(d, sidx)                                                \
    if (__any_sync(0xffffffffu, (d) < dist[0])) {                            \
        bool c0 = (d) < dist[0];                                             \
        bool c1 = (d) < dist[1];                                             \
        bool c2 = (d) < dist[2];                                             \
        bool c3 = (d) < dist[3];                                             \
        bool c4 = (d) < dist[4];                                             \
        bool c5 = (d) < dist[5];                                             \
        bool c6 = (d) < dist[6];                                             \
        bool c7 = (d) < dist[7];                                             \
        float n0 = c1 ? dist[1] : (c0 ? (d) : dist[0]);                      \
        int   m0 = c1 ? nidx[1] : (c0 ? (sidx) : nidx[0]);                   \
        float n1 = c2 ? dist[2] : (c1 ? (d) : dist[1]);                      \
        int   m1 = c2 ? nidx[2] : (c1 ? (sidx) : nidx[1]);                   \
        float n2 = c3 ? dist[3] : (c2 ? (d) : dist[2]);                      \
        int   m2 = c3 ? nidx[3] : (c2 ? (sidx) : nidx[2]);                   \
        float n3 = c4 ? dist[4] : (c3 ? (d) : dist[3]);                      \
        int   m3 = c4 ? nidx[4] : (c3 ? (sidx) : nidx[3]);                   \
        float n4 = c5 ? dist[5] : (c4 ? (d) : dist[4]);                      \
        int   m4 = c5 ? nidx[5] : (c4 ? (sidx) : nidx[4]);                   \
        float n5 = c6 ? dist[6] : (c5 ? (d) : dist[5]);                      \
        int   m5 = c6 ? nidx[6] : (c5 ? (sidx) : nidx[5]);                   \
        float n6 = c7 ? dist[7] : (c6 ? (d) : dist[6]);                      \
        int   m6 = c7 ? nidx[7] : (c6 ? (sidx) : nidx[6]);                   \
        float n7 = c7 ? (d) : dist[7];                                       \
        int   m7 = c7 ? (sidx) : nidx[7];                                    \
        dist[0] = n0; nidx[0] = m0;                                          \
        dist[1] = n1; nidx[1] = m1;                                          \
        dist[2] = n2; nidx[2] = m2;                                          \
        dist[3] = n3; nidx[3] = m3;                                          \
        dist[4] = n4; nidx[4] = m4;                                          \
        dist[5] = n5; nidx[5] = m5;                                          \
        dist[6] = n6; nidx[6] = m6;                                          \
        dist[7] = n7; nidx[7] = m7;                                          \
    }

__global__ void __launch_bounds__(128)
knn_kernel(const float* __restrict__ xyz,
           const float* __restrict__ sxyz) {
    __shared__ float4 sp[SS];   // 32 KB
    int b = blockIdx.y;

    const float* sb = sxyz + (size_t)b * 3 * SS;
    for (int s = threadIdx.x; s < SS; s += blockDim.x) {
        sp[s] = make_float4(sb[s], sb[SS + s], sb[2 * SS + s], 0.0f);
    }
    __syncthreads();

    int n = blockIdx.x * blockDim.x + threadIdx.x;
    const float* xb = xyz + (size_t)b * 3 * NPTS;
    float qx = xb[n];
    float qy = xb[NPTS + n];
    float qz = xb[2 * NPTS + n];

    float dist[KNN];     // descending: dist[0] = current max
    int   nidx[KNN];
    #pragma unroll
    for (int k = 0; k < KNN; k++) { dist[k] = 3.4e38f; nidx[k] = 0; }

    for (int s = 0; s < SS; s += 4) {
        float4 p0 = sp[s + 0];
        float4 p1 = sp[s + 1];
        float4 p2 = sp[s + 2];
        float4 p3 = sp[s + 3];
        float dx0 = qx - p0.x, dy0 = qy - p0.y, dz0 = qz - p0.z;
        float dx1 = qx - p1.x, dy1 = qy - p1.y, dz1 = qz - p1.z;
        float dx2 = qx - p2.x, dy2 = qy - p2.y, dz2 = qz - p2.z;
        float dx3 = qx - p3.x, dy3 = qy - p3.y, dz3 = qz - p3.z;
        float d0 = fmaf(dx0, dx0, fmaf(dy0, dy0, dz0 * dz0));
        float d1 = fmaf(dx1, dx1, fmaf(dy1, dy1, dz1 * dz1));
        float d2 = fmaf(dx2, dx2, fmaf(dy2, dy2, dz2 * dz2));
        float d3 = fmaf(dx3, dx3, fmaf(dy3, dy3, dz3 * dz3));
        float m = fminf(fminf(d0, d1), fminf(d2, d3));
        // One vote per 4 points; inserts stay in s-order inside.
        if (__any_sync(0xffffffffu, m < dist[0])) {
            INSERT_POINT(d0, s + 0)
            INSERT_POINT(d1, s + 1)
            INSERT_POINT(d2, s + 2)
            INSERT_POINT(d3, s + 3)
        }
    }

    // inverse-distance weights (reference formula)
    float inv[KNN];
    float ws = 0.0f;
    #pragma unroll
    for (int k = 0; k < KNN; k++) {
        float dd = sqrtf(dist[k]);
        dd = fmaxf(dd, 1e-10f);
        inv[k] = 1.0f / dd;
        ws += inv[k];
    }
    float rws = 1.0f / ws;

    int base = (b * NPTS + n) * KNN;
    #pragma unroll
    for (int k = 0; k < KNN; k++) {
        g_idx[base + k] = nidx[k];
        g_w[base + k]   = inv[k] * rws;
    }
}

// ---------------------------------------------------------------------------
// Kernel 2: weighted feature interpolation, fp16 gathers, fp32 accumulate.
// Block = 32 queries, 1024 threads.
// Phase 1: lanes span channels -> each (q,k) gather is 512B contiguous.
// Phase 2: warp per channel row, lanes along n -> coalesced fp32 STG.
// ---------------------------------------------------------------------------
__global__ void interp_kernel(float* __restrict__ out) {
    __shared__ float tile[32][CC + 1];   // 32 x 257 floats = 32.9 KB
    __shared__ int   s_idx[32][KNN];
    __shared__ float s_w[32][KNN];

    int b  = blockIdx.y;
    int n0 = blockIdx.x * 32;
    int tid = threadIdx.x;

    if (tid < 32 * KNN) {
        int nn = tid / KNN;
        int kk = tid % KNN;
        int base = (b * NPTS + n0 + nn) * KNN;
        s_idx[nn][kk] = g_idx[base + kk];
        s_w[nn][kk]   = g_w[base + kk];
    }
    __syncthreads();

    int tc    = tid & 63;
    int qbase = tid >> 6;            // 0..15, each handles 2 queries
    const __half* fb = g_featH + (size_t)b * SS * CC + tc * 4;

    #pragma unroll
    for (int q = qbase; q < 32; q += 16) {
        float a0 = 0.f, a1 = 0.f, a2 = 0.f, a3 = 0.f;
        #pragma unroll
        for (int k = 0; k < KNN; k++) {
            int   si = s_idx[q][k];
            float wt = s_w[q][k];
            uint2 raw = *(const uint2*)(fb + (size_t)si * CC);
            __half2 h0 = *reinterpret_cast<__half2*>(&raw.x);
            __half2 h1 = *reinterpret_cast<__half2*>(&raw.y);
            float2 f0 = __half22float2(h0);
            float2 f1 = __half22float2(h1);
            a0 = fmaf(wt, f0.x, a0);
            a1 = fmaf(wt, f0.y, a1);
            a2 = fmaf(wt, f1.x, a2);
            a3 = fmaf(wt, f1.y, a3);
        }
        int c = tc * 4;
        tile[q][c + 0] = a0;
        tile[q][c + 1] = a1;
        tile[q][c + 2] = a2;
        tile[q][c + 3] = a3;
    }
    __syncthreads();

    int lane = tid & 31;
    int w    = tid >> 5;
    float* ob = out + (size_t)b * CC * NPTS + n0 + lane;
    #pragma unroll
    for (int j = 0; j < 8; j++) {
        int c = w + j * 32;
        ob[(size_t)c * NPTS] = tile[lane][c];
    }
}

// ---------------------------------------------------------------------------
extern "C" void kernel_launch(void* const* d_in, const int* in_sizes, int n_in,
                              void* d_out, int out_size) {
    const float* xyz         = (const float*)d_in[0];  // [B,3,N]
    const float* sparse_xyz  = (const float*)d_in[1];  // [B,3,S]
    const float* sparse_feat = (const float*)d_in[2];  // [B,C,S]
    float* out = (float*)d_out;                        // [B,C,N]

    transpose_feat_kernel<<<dim3(SS / 32, CC / 32, BB), dim3(32, 8)>>>(sparse_feat);
    knn_kernel<<<dim3(NPTS / 128, BB), 128>>>(xyz, sparse_xyz);
    interp_kernel<<<dim3(NPTS / 32, BB), 1024>>>(out);
}